// round 2
// baseline (speedup 1.0000x reference)
#include <cuda_runtime.h>
#include <math.h>

// ---------------------------------------------------------------------------
// ASSR reconstruction loss, fully fused, single pass over pred/target.
//   pix  = mean|pred - target|                  (32,3,512,512)
//   lr   = mean|bicubicAA_down4(pred) - lr_ref| (32,3,128,128)
//   out  = { pix + 0.1*lr, pix, lr, lr, 0 }
//
// Bicubic antialias (a=-0.75), scale=4, align_corners=False: every output
// uses the same 16-tap window (sum = 4.0 exactly); border replicate folds
// clamped taps into rows/cols 0 and 511 only (closed-form sums WA..WD).
// ---------------------------------------------------------------------------

#define HW       512
#define OUTHW    128
#define NBC      96            // 32 batch * 3 channels
#define RPS      32            // output rows per split (block)
#define SPLITS   (OUTHW / RPS) // 4
#define THREADS  256           // each thread owns 2 columns (float2)
#define NBLOCKS  (SPLITS * NBC)

// normalized taps (raw cubic values are dyadic; raw window sum = 4.0 exactly)
#define WT0 (-0.0025634765625f)
#define WT1 (-0.0164794921875f)
#define WT2 (-0.0274658203125f)
#define WT3 (-0.0179443359375f)
#define WT4 ( 0.0286865234375f)
#define WT5 ( 0.1065673828125f)
#define WT6 ( 0.1873779296875f)
#define WT7 ( 0.2418212890625f)
// border-folded sums (replicate clamp)
#define WA  ( 0.2581787109375f)  // sum wt[0..6]
#define WB  (-0.0465087890625f)  // sum wt[0..2]
#define WC  WB                   // sum wt[13..15] (symmetry)
#define WD  WA                   // sum wt[9..15]

__constant__ float c_wt[16] = {WT0,WT1,WT2,WT3,WT4,WT5,WT6,WT7,
                               WT7,WT6,WT5,WT4,WT3,WT2,WT1,WT0};

// per-block partials (every block writes its slot each call -> no zeroing)
__device__ double g_pp[NBLOCKS];
__device__ double g_pl[NBLOCKS];

__global__ __launch_bounds__(THREADS)
void assr_fused_kernel(const float* __restrict__ pred,
                       const float* __restrict__ tgt,
                       const float* __restrict__ lrr)
{
    extern __shared__ float sh[];
    float* vrows = sh;                 // [RPS][512] vertical-resized rows
    float* red   = sh + RPS * HW;      // [32] reduction scratch

    const int t   = threadIdx.x;       // 0..255, owns columns 2t, 2t+1
    const int s   = blockIdx.x;        // split 0..3
    const int bc  = blockIdx.y;        // 0..95
    const int oh0 = RPS * s;

    const float2* P2 = reinterpret_cast<const float2*>(pred + (size_t)bc * (HW * HW)) + t;
    const float2* T2 = reinterpret_cast<const float2*>(tgt  + (size_t)bc * (HW * HW)) + t;
    const int RS = HW / 2;             // row stride in float2

    // ---------------- vertical polyphase FIR + pix reduction ---------------
    // Group k covers input rows h = 4k..4k+3, scattering into outputs
    // oh = k-2..k+2 with static per-phase tap patterns. A[i] <-> oh = k+(i-2).
    float2 A0 = {0.f,0.f}, A1 = {0.f,0.f}, A2 = {0.f,0.f},
           A3 = {0.f,0.f}, A4 = {0.f,0.f};
    float pixs = 0.f;

    #pragma unroll
    for (int kk = 0; kk < RPS + 4; ++kk) {
        const int k  = oh0 - 2 + kk;
        const int hb = 4 * k;
        if (hb >= 0 && hb < HW) {
            const float2* pp = P2 + (size_t)hb * RS;
            const float2 p0 = pp[0];
            const float2 p1 = pp[RS];
            const float2 p2 = pp[2 * RS];
            const float2 p3 = pp[3 * RS];
            if (kk >= 2 && kk < 2 + RPS) {   // core rows: count pix exactly once
                const float2* tp = T2 + (size_t)hb * RS;
                const float2 t0 = tp[0], t1 = tp[RS], t2 = tp[2*RS], t3 = tp[3*RS];
                pixs += fabsf(p0.x - t0.x) + fabsf(p0.y - t0.y)
                      + fabsf(p1.x - t1.x) + fabsf(p1.y - t1.y)
                      + fabsf(p2.x - t2.x) + fabsf(p2.y - t2.y)
                      + fabsf(p3.x - t3.x) + fabsf(p3.y - t3.y);
            }
            // phase r=0: taps 14,10,6,2 -> oh k-2..k+1
            if (hb == 0) {
                A2.x += WA * p0.x; A2.y += WA * p0.y;
                A3.x += WB * p0.x; A3.y += WB * p0.y;     // border fold
            } else {
                A0.x += WT1 * p0.x; A0.y += WT1 * p0.y;
                A1.x += WT5 * p0.x; A1.y += WT5 * p0.y;
                A2.x += WT6 * p0.x; A2.y += WT6 * p0.y;
                A3.x += WT2 * p0.x; A3.y += WT2 * p0.y;
            }
            // phase r=1: taps 15,11,7,3 -> oh k-2..k+1
            A0.x += WT0 * p1.x; A0.y += WT0 * p1.y;
            A1.x += WT4 * p1.x; A1.y += WT4 * p1.y;
            A2.x += WT7 * p1.x; A2.y += WT7 * p1.y;
            A3.x += WT3 * p1.x; A3.y += WT3 * p1.y;
            // phase r=2: taps 12,8,4,0  -> oh k-1..k+2
            A1.x += WT3 * p2.x; A1.y += WT3 * p2.y;
            A2.x += WT7 * p2.x; A2.y += WT7 * p2.y;
            A3.x += WT4 * p2.x; A3.y += WT4 * p2.y;
            A4.x += WT0 * p2.x; A4.y += WT0 * p2.y;
            // phase r=3: taps 13,9,5,1  -> oh k-1..k+2
            if (hb == HW - 4) {
                A1.x += WC * p3.x; A1.y += WC * p3.y;     // border fold
                A2.x += WD * p3.x; A2.y += WD * p3.y;
            } else {
                A1.x += WT2 * p3.x; A1.y += WT2 * p3.y;
                A2.x += WT6 * p3.x; A2.y += WT6 * p3.y;
                A3.x += WT5 * p3.x; A3.y += WT5 * p3.y;
                A4.x += WT1 * p3.x; A4.y += WT1 * p3.y;
            }
        }
        const int oh = k - 2;                 // A0 complete after group k
        if (oh >= oh0 && oh < oh0 + RPS)
            reinterpret_cast<float2*>(vrows + (oh - oh0) * HW)[t] = A0;
        A0 = A1; A1 = A2; A2 = A3; A3 = A4; A4.x = 0.f; A4.y = 0.f;
    }
    __syncthreads();

    // ---------------- horizontal FIR from smem + lr reduction --------------
    float lrs = 0.f;
    const int ow = t & (OUTHW - 1);
    const int r0 = t >> 7;                      // 0..1; rows r0, r0+2, ...
    const float* lrbase = lrr + (size_t)bc * (OUTHW * OUTHW)
                              + (size_t)oh0 * OUTHW + ow;

    if (ow >= 2 && ow < OUTHW - 2) {
        // interior: 5 aligned, conflict-free LDS.128 per output
        #pragma unroll
        for (int i = 0; i < RPS / 2; ++i) {
            const int rr = r0 + 2 * i;
            const float4* v =
                reinterpret_cast<const float4*>(vrows + rr * HW) + (ow - 2);
            const float4 a = v[0], b = v[1], c = v[2], d = v[3], e = v[4];
            float acc = a.z * WT0 + a.w * WT1
                      + b.x * WT2 + b.y * WT3 + b.z * WT4 + b.w * WT5
                      + c.x * WT6 + c.y * WT7 + c.z * WT7 + c.w * WT6
                      + d.x * WT5 + d.y * WT4 + d.z * WT3 + d.w * WT2
                      + e.x * WT1 + e.y * WT0;
            lrs += fabsf(acc - lrbase[rr * OUTHW]);
        }
    } else {
        // border ow in {0,1,126,127}: scalar clamped gather (replicate fold)
        for (int i = 0; i < RPS / 2; ++i) {
            const int rr = r0 + 2 * i;
            const float* row = vrows + rr * HW;
            float acc = 0.f;
            #pragma unroll
            for (int tt = 0; tt < 16; ++tt) {
                int src = 4 * ow - 6 + tt;
                src = src < 0 ? 0 : (src > HW - 1 ? HW - 1 : src);
                acc += c_wt[tt] * row[src];
            }
            lrs += fabsf(acc - lrbase[rr * OUTHW]);
        }
    }

    // ---------------- block reduction -> per-block partial slot ------------
    #pragma unroll
    for (int o = 16; o; o >>= 1) {
        pixs += __shfl_xor_sync(0xffffffffu, pixs, o);
        lrs  += __shfl_xor_sync(0xffffffffu, lrs,  o);
    }
    const int wid = t >> 5, lane = t & 31;
    if (lane == 0) { red[wid] = pixs; red[16 + wid] = lrs; }
    __syncthreads();
    if (t == 0) {
        double ps = 0.0, ls = 0.0;
        #pragma unroll
        for (int i = 0; i < THREADS / 32; ++i) {
            ps += (double)red[i];
            ls += (double)red[16 + i];
        }
        const int slot = bc * SPLITS + s;
        g_pp[slot] = ps;
        g_pl[slot] = ls;
    }
}

__global__ __launch_bounds__(NBLOCKS)
void finalize_kernel(float* __restrict__ out, int out_size) {
    __shared__ double sp[NBLOCKS / 32], sl[NBLOCKS / 32];
    const int t = threadIdx.x;
    double p = g_pp[t];
    double l = g_pl[t];
    #pragma unroll
    for (int o = 16; o; o >>= 1) {
        p += __shfl_xor_sync(0xffffffffu, p, o);
        l += __shfl_xor_sync(0xffffffffu, l, o);
    }
    if ((t & 31) == 0) { sp[t >> 5] = p; sl[t >> 5] = l; }
    __syncthreads();
    if (t == 0) {
        double ps = 0.0, ls = 0.0;
        #pragma unroll
        for (int i = 0; i < NBLOCKS / 32; ++i) { ps += sp[i]; ls += sl[i]; }
        const double pix     = ps / 25165824.0;   // 32*3*512*512
        const double lr      = ls / 1572864.0;    // 32*3*128*128
        const double consist = lr;                // LAM_LR*lr + LAM_PAIR*0
        const double total   = pix + 0.1 * consist;
        float vals[5] = {(float)total, (float)pix, (float)consist, (float)lr, 0.f};
        for (int i = 0; i < out_size; ++i)
            out[i] = (i < 5) ? vals[i] : 0.f;
    }
}

extern "C" void kernel_launch(void* const* d_in, const int* in_sizes, int n_in,
                              void* d_out, int out_size)
{
    const float* pred = (const float*)d_in[0];
    const float* tgt  = (const float*)d_in[1];
    const float* lrr  = (const float*)d_in[2];
    // d_in[3] (scale) is uniform 4.0 -> static sizes, unused.

    const size_t smem = (size_t)(RPS * HW + 32) * sizeof(float);  // 65,664 B
    cudaFuncSetAttribute(assr_fused_kernel,
                         cudaFuncAttributeMaxDynamicSharedMemorySize, (int)smem);

    const dim3 grid(SPLITS, NBC);
    assr_fused_kernel<<<grid, THREADS, smem>>>(pred, tgt, lrr);
    finalize_kernel<<<1, NBLOCKS>>>((float*)d_out, out_size);
}